// round 11
// baseline (speedup 1.0000x reference)
#include <cuda_runtime.h>
#include <cuda_fp16.h>
#include <cstdint>

#define TS 1460
#define NG 2000
#define NREC 16      // uint32 slots per (t,g) record (64B)
#define TCH 16       // timesteps per routing thread

// ---- scratch (static __device__ globals) ----
__device__ float         g_pre [(size_t)TS * NG * NREC];   // ~187 MB
__device__ unsigned char g_gate[(size_t)TS * NG];
__device__ float2        g_sb  [(size_t)TS * NG];          // surf, base interleaved
__device__ float         g_uh  [2 * 15 * NG];
__device__ float         g_cc  [NG * 16];                  // per-cell folded constants

__constant__ float c_lo[32] = {0.f,0.5f,0.001f,0.3f,20.f,-8.f,1.f,0.1f,0.1f,1e-4f,1.f,1e-4f,0.1f,0.1f,50.f,-8.f,
                               1.f,-5.f,0.f,1.5f,0.f,0.01f,-1.f,0.f,0.f,0.f,50.f,50.f,0.3f,0.01f,0.5f,0.15f};
__constant__ float c_hi[32] = {1.f,3.f,3.f,1.f,300.f,-2.f,5.f,200.f,0.5f,0.9999f,50.f,0.9999f,50.f,100.f,500.f,-2.f,
                               5.f,2.f,5.f,3.f,5.f,0.2f,1.f,0.4f,1.f,1.f,500.f,500.f,20.f,5.f,13.f,1.5f};

__device__ __forceinline__ float sigm(float x) { return 1.f / (1.f + __expf(-x)); }
__device__ __forceinline__ float clip01(float x) { return fminf(fmaxf(x, 1e-6f), 1.f); }
__device__ __forceinline__ void prefetchL2(const void* p) {
    asm volatile("prefetch.global.L2 [%0];" :: "l"(p));
}
// expm1 for x in [0, 0.5]: Horner, rel err < 4e-6.
__device__ __forceinline__ float expm1_poly(float x) {
    float r = 1.f/720.f;
    r = fmaf(r, x, 1.f/120.f);
    r = fmaf(r, x, 1.f/24.f);
    r = fmaf(r, x, 1.f/6.f);
    r = fmaf(r, x, 0.5f);
    r = fmaf(r, x, 1.f);
    return r * x;
}
__device__ __forceinline__ float2 h2pair(float v) {
    unsigned u = __float_as_uint(v);
    __half2 h = *reinterpret_cast<__half2*>(&u);
    return __half22float2(h);
}
__device__ __forceinline__ unsigned packh2(float a, float b) {
    __half2 h = __floats2half2_rn(a, b);
    return *reinterpret_cast<unsigned*>(&h);
}

// ============================================================================
// Kernel A: per-cell constants — UH weights + folded scan/prep constants.
// ============================================================================
__global__ void cellconst_kernel(const float* __restrict__ hyb) {
    int g = blockIdx.x * blockDim.x + threadIdx.x;
    if (g >= NG) return;
    const float* h = hyb + (size_t)g * 32;
    float P[32];
#pragma unroll
    for (int i = 0; i < 32; i++) P[i] = c_lo[i] + sigm(h[i]) * (c_hi[i] - c_lo[i]);

    // folded constants for prep
    float* cc = g_cc + (size_t)g * 16;
    cc[0]  = P[24] * (1.f - P[25]);                    // canopy coef
    cc[1]  = P[18];                                    // Kf
    cc[2]  = P[17];                                    // Tbf
    cc[3]  = P[22];                                    // Tbm
    cc[4]  = P[0];                                     // inf_pc
    cc[5]  = P[3];                                     // hm_a
    cc[6]  = exp2f(P[5] * 3.3219280948873623f);        // p10a
    cc[7]  = P[7];                                     // bfmax1
    cc[8]  = P[7] / expm1f(P[8]);                      // c_lam
    cc[9]  = P[7] / (1.f - P[9]);                      // c_th
    cc[10] = exp2f(P[15] * 3.3219280948873623f);       // p10b
    cc[11] = P[13];                                    // bfmax2
    cc[12] = 0.f; cc[13] = 0.f; cc[14] = 0.f; cc[15] = 0.f;

    // UH weights
    float a1 = P[28], b1 = P[29], a2 = P[30], b2 = P[31];
    float ib1 = 1.f / b1, ib2 = 1.f / b2;
    float lw1[15], lw2[15], m1 = -1e30f, m2 = -1e30f;
#pragma unroll
    for (int k = 0; k < 15; k++) {
        float kk = (float)(k + 1);
        float lk = __logf(kk);
        lw1[k] = (a1 - 1.f) * lk - kk * ib1;
        lw2[k] = (a2 - 1.f) * lk - kk * ib2;
        m1 = fmaxf(m1, lw1[k]); m2 = fmaxf(m2, lw2[k]);
    }
    float e1[15], e2[15], s1 = 0.f, s2 = 0.f;
#pragma unroll
    for (int k = 0; k < 15; k++) {
        e1[k] = __expf(lw1[k] - m1); s1 += e1[k];
        e2[k] = __expf(lw2[k] - m2); s2 += e2[k];
    }
    float i1 = 1.f / s1, i2 = 1.f / s2;
#pragma unroll
    for (int k = 0; k < 15; k++) {
        g_uh[k * NG + g]        = e1[k] * i1;
        g_uh[(15 + k) * NG + g] = e2[k] * i2;
    }
}

// ============================================================================
// Kernel B: per-(t,g) preprocess — softmax + constant folding + forcing
// precompute. 64B record = 4 coalesced LDG.128 in the scan:
//  h2: [k0,wi1] [wi2,wi3'] [wi4,wa0] [wa1',wa2'] [wa3',wa4'] [wa5',wb0]
//      [wb1',wb2'] [wb3',wb4'] [wb5',--]
//  u9=bits  u10=rain_eff u11=snowf_eff u12=refreeze_cap u13=ddf_pos u14=pet
// ============================================================================
__global__ void prep_kernel(const float* __restrict__ xphy, const float* __restrict__ wts) {
    size_t i = (size_t)blockIdx.x * blockDim.x + threadIdx.x;
    if (i >= (size_t)TS * NG) return;
    int g = (int)(i % NG);
    const float4* wsrc = (const float4*)(wts + i * 24);
    float v[24];
#pragma unroll
    for (int k = 0; k < 6; k++) {
        float4 q = wsrc[k];
        v[4*k] = q.x; v[4*k+1] = q.y; v[4*k+2] = q.z; v[4*k+3] = q.w;
    }
    float w[18];
#pragma unroll
    for (int grp = 0; grp < 3; grp++) {
        float m = v[grp*6];
#pragma unroll
        for (int k = 1; k < 6; k++) m = fmaxf(m, v[grp*6 + k]);
        float e[6], s = 0.f;
#pragma unroll
        for (int k = 0; k < 6; k++) { e[k] = __expf(v[grp*6 + k] - m); s += e[k]; }
        float inv = 1.f / s;
#pragma unroll
        for (int k = 0; k < 6; k++) w[grp*6 + k] = e[k] * inv;
    }
    unsigned bits = 0;
#pragma unroll
    for (int k = 0; k < 6; k++) bits |= (v[18 + k] > 0.f) ? (1u << k) : 0u;

    // per-cell folded constants (L2-resident table)
    const float4* ccp = (const float4*)(g_cc + (size_t)g * 16);
    float4 q0 = ccp[0], q1 = ccp[1], q2 = ccp[2];
    const float cc = q0.x, Kf = q0.y, Tbf = q0.z, Tbm = q0.w;
    const float inf_pc = q1.x, hm_a = q1.y, p10a = q1.z, bfmax1 = q1.w;
    const float c_lam = q2.x, c_th = q2.y, p10b = q2.z, bfmax2 = q2.w;

    const float prcp = xphy[i*3 + 0], temp = xphy[i*3 + 1], pet = xphy[i*3 + 2];
    // state-independent forcing
    float canopy = pet * cc;
    float gb2 = ((bits >> 2) & 1u) ? 1.f : 0.f;
    float gb3 = ((bits >> 3) & 1u) ? 1.f : 0.f;
    float rain_eff  = (temp >= 0.f) ? fmaxf(prcp - canopy * gb2, 0.f) : 0.f;
    float snowf_eff = (temp <  0.f) ? fmaxf(prcp - canopy * gb3, 0.f) : 0.f;
    float refreeze_cap = Kf * fmaxf(Tbf - temp, 0.f);
    float ddf_pos = fmaxf(temp - Tbm, 0.f);

    // folded weights
    float k0 = fmaf(w[0], inf_pc, w[1] + w[4] + w[5]);
    unsigned o[16];
    o[0] = packh2(k0, w[1]);
    o[1] = packh2(w[2], w[3] * hm_a);
    o[2] = packh2(w[4], w[6]);
    o[3] = packh2(w[7] * p10a,  w[8] * bfmax1);
    o[4] = packh2(w[9] * bfmax1, w[10] * c_lam);
    o[5] = packh2(w[11] * c_th, w[12]);
    o[6] = packh2(w[13] * p10b, w[14] * bfmax2);
    o[7] = packh2(w[15] * bfmax2, w[16] * bfmax2);
    o[8] = packh2(w[17] * p10b, 0.f);
    o[9]  = bits;
    o[10] = __float_as_uint(rain_eff);
    o[11] = __float_as_uint(snowf_eff);
    o[12] = __float_as_uint(refreeze_cap);
    o[13] = __float_as_uint(ddf_pos);
    o[14] = __float_as_uint(pet);
    o[15] = 0u;

    float4* dst = (float4*)(g_pre + i * NREC);
#pragma unroll
    for (int k = 0; k < 4; k++)
        dst[k] = make_float4(__uint_as_float(o[4*k]), __uint_as_float(o[4*k+1]),
                             __uint_as_float(o[4*k+2]), __uint_as_float(o[4*k+3]));
    g_gate[i] = (unsigned char)bits;
}

// ============================================================================
// Kernel C: sequential scan — 1 cell/thread, one warp per SM, depth-2
// register pipeline + L2 prefetch. State-independent work removed.
// ============================================================================
__global__ void __launch_bounds__(32, 1) scan_kernel(const float* __restrict__ hyb) {
    int g = blockIdx.x * 32 + threadIdx.x;
    if (g >= NG) return;
    const float* h = hyb + (size_t)g * 32;
    float P[32];
#pragma unroll
    for (int i = 0; i < 32; i++) P[i] = c_lo[i] + sigm(h[i]) * (c_hi[i] - c_lo[i]);

    const float ddfmin = P[19], ddfplus = P[20], Kcum = P[21], swi = P[23];
    const float msw1 = P[26];
    const float inv_m1 = 1.f / P[26], inv_m2 = 1.f / P[27];
    const float hbv_beta = P[1], vic_b = P[2];
    const float perc_coef = P[10] / (1.f - P[11]);
    const float perc_sfc = P[11], crise = P[12];
    const float inv_x3a = 1.f / P[4];
    const float bfn1 = P[6], lam = P[8], thresh = P[9];
    const float inv_x3b = 1.f / P[14];
    const float bfn2 = P[16];

    float snow = 1e-6f, liq = 1e-6f, cum = 1e-6f, sw1 = 1e-6f, sw2 = 1e-6f;

    const float4* rec = (const float4*)g_pre;
    size_t r0 = ((size_t)0 * NG + g) * 4;
    size_t r1 = ((size_t)1 * NG + g) * 4;
    float4 c0 = __ldcs(rec+r0), c1 = __ldcs(rec+r0+1), c2 = __ldcs(rec+r0+2), c3 = __ldcs(rec+r0+3);
    float4 n0 = __ldcs(rec+r1), n1 = __ldcs(rec+r1+1), n2 = __ldcs(rec+r1+2), n3 = __ldcs(rec+r1+3);
#pragma unroll
    for (int tp = 2; tp < 8; tp++)
        prefetchL2((const char*)(rec + ((size_t)tp * NG + g) * 4));

    for (int t = 0; t < TS; t++) {
        int tpf = t + 8; if (tpf >= TS) tpf = TS - 1;
        prefetchL2((const char*)(rec + ((size_t)tpf * NG + g) * 4));

        int t2 = t + 2; if (t2 >= TS) t2 = TS - 1;
        size_t r2 = ((size_t)t2 * NG + g) * 4;
        float4 m0 = __ldcs(rec+r2),   m1v = __ldcs(rec+r2+1),
               m2v = __ldcs(rec+r2+2), m3 = __ldcs(rec+r2+3);

        // unpack
        float2 p0 = h2pair(c0.x), p1 = h2pair(c0.y), p2 = h2pair(c0.z);
        float2 p3 = h2pair(c0.w), p4 = h2pair(c1.x), p5 = h2pair(c1.y);
        float2 p6 = h2pair(c1.z), p7 = h2pair(c1.w), p8 = h2pair(c2.x);
        const float k0 = p0.x,  wi1 = p0.y, wi2 = p1.x, wi3f = p1.y, wi4 = p2.x;
        const float wa0 = p2.y, wa1f = p3.x, wa2f = p3.y, wa3f = p4.x, wa4f = p4.y, wa5f = p5.x;
        const float wb0 = p5.y, wb1f = p6.x, wb2f = p6.y, wb3f = p7.x, wb4f = p7.y, wb5f = p8.x;
        const unsigned bits = __float_as_uint(c2.y);
        const float rain_eff = c2.z, snowf_eff = c2.w;
        const float refreeze_cap = c3.x, ddf_pos = c3.y, pet = c3.z;
        const float gb0 = (bits & 1u)        ? 1.f : 0.f;
        const float gb1 = ((bits >> 1) & 1u) ? 1.f : 0.f;

        // --- snow module (state-dependent part only) ---
        float refreeze = fminf(liq, refreeze_cap);
        snow = snow + snowf_eff + refreeze;
        liq  = liq - refreeze;
        float ddf  = ddfmin + ddfplus * (1.f - __expf(-Kcum * cum));
        float melt = fminf(snow, ddf * ddf_pos);
        snow -= melt;
        cum = (snow < 1e-6f) ? 1e-6f : (cum + melt);
        liq += melt;
        float overflow = fmaxf(liq - swi * snow, 0.f);
        liq -= overflow;
        float wavail = rain_eff + overflow;

        // --- infiltration blend (constants folded) ---
        float sat1 = clip01(sw1 * inv_m1);
        float dry1 = clip01(1.f - sat1);
        float o1 = __powf(sat1, hbv_beta);
        float o2 = __powf(dry1, vic_b);
        float fsum = k0 - wi1 * o1 + wi2 * o2 + wi3f * dry1 - wi4 * (sat1 * sat1);
        float infil = wavail * fsum;
        sw1 += infil;
        float excess = fmaxf(sw1 - msw1, 0.f);
        sw1 -= excess;
        float surf = wavail - infil + excess;

        // --- percolation / capillary rise / ET ---
        sat1 = clip01(sw1 * inv_m1);
        float perc = gb0 * perc_coef * fmaxf(sat1 - perc_sfc, 0.f);
        perc = fminf(perc, sw1);
        sw1 -= perc; sw2 += perc;
        float sat2 = clip01(sw2 * inv_m2);
        sat1 = clip01(sw1 * inv_m1);
        float capi = fminf(gb1 * crise * (1.f - sat1) * sat2, sw2);
        sw2 -= capi; sw1 += capi;
        sat1 = clip01(sw1 * inv_m1);
        float et = fminf(pet * sat1, sw1);
        sw1 -= et;
        sat1 = clip01(sw1 * inv_m1);

        // --- baseflow 1 (folded weights) ---
        float ra = sw1 * inv_x3a; float ra2 = ra * ra; float qa = 1.f + ra2 * ra2;
        float b0v = sw1 * (1.f - sqrtf(rsqrtf(qa)));
        float pw1 = __powf(sat1, bfn1);
        float em  = expm1_poly(lam * sat1);
        float th  = fmaxf(sat1 - thresh, 0.f);
        float bf1 = wa0*b0v + wa1f*sw1 + wa2f*pw1 + wa3f*sat1 + wa4f*em + wa5f*th;
        bf1 = fminf(bf1, sw1);
        sw1 -= bf1;

        // --- baseflow 2 (folded weights) ---
        float s2c = clip01(sw2 * inv_m2);
        float rb = sw2 * inv_x3b; float rb2 = rb * rb; float qb = 1.f + rb2 * rb2;
        float d0 = sw2 * (1.f - sqrtf(rsqrtf(qb)));
        float pw2 = __powf(s2c, bfn2);
        float bf2 = wb0*d0 + wb1f*sw2 + wb2f*pw2 + wb3f*s2c + wb4f*(s2c*s2c) + wb5f*(sw2*s2c);
        bf2 = fminf(bf2, sw2);
        sw2 -= bf2;

        g_sb[(size_t)t * NG + g] = make_float2(surf, bf1 + bf2);

        c0 = n0; c1 = n1; c2 = n2; c3 = n3;
        n0 = m0; n1 = m1v; n2 = m2v; n3 = m3;
    }
}

// ============================================================================
// Kernel D: 15-tap UH routing + gating + final sum (float2 loads).
// ============================================================================
__global__ void __launch_bounds__(128) route_kernel(float* __restrict__ out) {
    int g  = blockIdx.x * 128 + threadIdx.x;
    int t0 = blockIdx.y * TCH;
    if (g >= NG) return;
    float u1[15], u2[15];
#pragma unroll
    for (int k = 0; k < 15; k++) {
        u1[k] = g_uh[k * NG + g];
        u2[k] = g_uh[(15 + k) * NG + g];
    }
    float s[TCH + 14], b[TCH + 14];
#pragma unroll
    for (int i = 0; i < TCH + 14; i++) {
        int tt = t0 - 14 + i;
        bool ok = (tt >= 0) && (tt < TS);
        float2 v = ok ? g_sb[(size_t)tt * NG + g] : make_float2(0.f, 0.f);
        s[i] = v.x; b[i] = v.y;
    }
#pragma unroll
    for (int j = 0; j < TCH; j++) {
        int t = t0 + j;
        if (t < TS) {
            float cs = 0.f, cb = 0.f;
#pragma unroll
            for (int l = 0; l < 15; l++) {
                cs += u1[l] * s[14 + j - l];
                cb += u2[l] * b[14 + j - l];
            }
            unsigned bits = g_gate[(size_t)t * NG + g];
            float g4 = (float)((bits >> 4) & 1);
            float g5 = (float)((bits >> 5) & 1);
            out[(size_t)t * NG + g] = g4 * cs + (1.f - g4) * s[14 + j]
                                    + g5 * cb + (1.f - g5) * b[14 + j];
        }
    }
}

// ============================================================================
extern "C" void kernel_launch(void* const* d_in, const int* in_sizes, int n_in,
                              void* d_out, int out_size) {
    const float* xphy = nullptr; const float* wts = nullptr; const float* hyb = nullptr;
    for (int i = 0; i < n_in; i++) {
        if (in_sizes[i] == TS * NG * 3)       xphy = (const float*)d_in[i];
        else if (in_sizes[i] == TS * NG * 24) wts  = (const float*)d_in[i];
        else if (in_sizes[i] == NG * 32)      hyb  = (const float*)d_in[i];
    }
    float* out = (float*)d_out;                  // (1460, 2000)

    size_t total = (size_t)TS * NG;
    cellconst_kernel<<<(NG + 127) / 128, 128>>>(hyb);
    prep_kernel<<<(unsigned)((total + 255) / 256), 256>>>(xphy, wts);
    scan_kernel<<<(NG + 31) / 32, 32>>>(hyb);
    dim3 rg((NG + 127) / 128, (TS + TCH - 1) / TCH);
    route_kernel<<<rg, 128>>>(out);
}